// round 10
// baseline (speedup 1.0000x reference)
#include <cuda_runtime.h>

// StructNDeconv2D: depthwise conv_transpose2d (K=3, stride=2, pad=1) normalized
// convolution. OH = 2H-1 = 511 so every tap is in bounds.
//
// Round-10 = Round-9 (proven: dense shifted-partition STG.128 stores, 4 output
// rows x 4 output cols per thread, fused softplus prep) with the input path
// replaced by block-cooperative smem staging:
//   - block loads its 9-row x 132-col x 2-array input region with fully dense
//     LDG.128 (~2.3 per thread) into smem,
//   - threads then read their 4-col windows as LDS.64 (2-cyc LSU floor, no
//     L1tex wavefront inflation).
// This cuts LSU issue cycles ~30% on the load side and removes the 2x
// half-dense load wavefronts that kept DRAM at 73.7%.

#define EPS_F 1e-20f

struct Wts {
    float s0, s1, s2, s3, s4, s5, s6, s7, s8;
    float ree, reo, roe, roo, b;
};

// ---- per-pixel math -------------------------------------------------------
__device__ __forceinline__ void pixE(float cv, float dv, const Wts& w,
                                     float& dd, float& cc) {
    float den = w.s4 * cv;
    dd = __fdividef(den * dv, den + EPS_F) + w.b;
    cc = den * w.ree;
}
__device__ __forceinline__ void pixO(float cL, float dL, float cR, float dR,
                                     const Wts& w, float& dd, float& cc) {
    float a = w.s3 * cR, b2 = w.s5 * cL;
    float den = a + b2;
    dd = __fdividef(fmaf(a, dR, b2 * dL), den + EPS_F) + w.b;
    cc = den * w.reo;
}
__device__ __forceinline__ void pixE2(float c0, float d0, float c1, float d1,
                                      const Wts& w, float& dd, float& cc) {
    float a = w.s1 * c1, b2 = w.s7 * c0;
    float den = a + b2;
    dd = __fdividef(fmaf(a, d1, b2 * d0), den + EPS_F) + w.b;
    cc = den * w.roe;
}
__device__ __forceinline__ void pixO2(float c0L, float d0L, float c0R, float d0R,
                                      float c1L, float d1L, float c1R, float d1R,
                                      const Wts& w, float& dd, float& cc) {
    float t0 = w.s0 * c1R, t2 = w.s2 * c1L, t6 = w.s6 * c0R, t8 = w.s8 * c0L;
    float den = (t0 + t2) + (t6 + t8);
    dd = __fdividef(fmaf(t0, d1R, fmaf(t2, d1L, fmaf(t6, d0R, t8 * d0L))),
                    den + EPS_F) + w.b;
    cc = den * w.roo;
}

// ---- 4-col chunks (outputs [S+4q, S+4q+4), window = input cols [2q..2q+3]) -
template<int S>
__device__ __forceinline__ void even_chunk(const float* cv, const float* dv,
                                           const Wts& w, float* o, float* co) {
    constexpr int h = S >> 1;
    if constexpr ((S & 1) == 0) {
        pixE(cv[h],   dv[h],                     w, o[0], co[0]);
        pixO(cv[h],   dv[h],   cv[h+1], dv[h+1], w, o[1], co[1]);
        pixE(cv[h+1], dv[h+1],                   w, o[2], co[2]);
        pixO(cv[h+1], dv[h+1], cv[h+2], dv[h+2], w, o[3], co[3]);
    } else {
        pixO(cv[h],   dv[h],   cv[h+1], dv[h+1], w, o[0], co[0]);
        pixE(cv[h+1], dv[h+1],                   w, o[1], co[1]);
        pixO(cv[h+1], dv[h+1], cv[h+2], dv[h+2], w, o[2], co[2]);
        pixE(cv[h+2], dv[h+2],                   w, o[3], co[3]);
    }
}
template<int S>
__device__ __forceinline__ void odd_chunk(const float* c0, const float* d0,
                                          const float* c1, const float* d1,
                                          const Wts& w, float* o, float* co) {
    constexpr int h = S >> 1;
    if constexpr ((S & 1) == 0) {
        pixE2(c0[h],   d0[h],   c1[h],   d1[h],   w, o[0], co[0]);
        pixO2(c0[h],   d0[h],   c0[h+1], d0[h+1],
              c1[h],   d1[h],   c1[h+1], d1[h+1], w, o[1], co[1]);
        pixE2(c0[h+1], d0[h+1], c1[h+1], d1[h+1], w, o[2], co[2]);
        pixO2(c0[h+1], d0[h+1], c0[h+2], d0[h+2],
              c1[h+1], d1[h+1], c1[h+2], d1[h+2], w, o[3], co[3]);
    } else {
        pixO2(c0[h],   d0[h],   c0[h+1], d0[h+1],
              c1[h],   d1[h],   c1[h+1], d1[h+1], w, o[0], co[0]);
        pixE2(c0[h+1], d0[h+1], c1[h+1], d1[h+1], w, o[1], co[1]);
        pixO2(c0[h+1], d0[h+1], c0[h+2], d0[h+2],
              c1[h+1], d1[h+1], c1[h+2], d1[h+2], w, o[2], co[2]);
        pixE2(c0[h+2], d0[h+2], c1[h+2], d1[h+2], w, o[3], co[3]);
    }
}

__device__ __forceinline__ void st4(float* p, const float* v) {
    __stcs(reinterpret_cast<float4*>(p), make_float4(v[0], v[1], v[2], v[3]));
}

// Thread's 4 output rows (oy = 4ry + p). Input rows cv[0..2] = y0..y0+2.
template<int SB>
__device__ __forceinline__ void doRows(const float cv[3][4], const float dv[3][4],
                                       const Wts& w, float* __restrict__ out,
                                       size_t N, size_t row0, int q, bool pm) {
    float o[4], co[4];
    size_t base = row0 + 4 * (size_t)q;

    even_chunk<SB>(cv[0], dv[0], w, o, co);
    st4(out + base + SB, o);
    st4(out + N + base + SB, co);

    odd_chunk<(SB + 1) & 3>(cv[0], dv[0], cv[1], dv[1], w, o, co);
    base += 511;
    st4(out + base + ((SB + 1) & 3), o);
    st4(out + N + base + ((SB + 1) & 3), co);

    even_chunk<(SB + 2) & 3>(cv[1], dv[1], w, o, co);
    base += 511;
    st4(out + base + ((SB + 2) & 3), o);
    st4(out + N + base + ((SB + 2) & 3), co);

    if (pm) {
        odd_chunk<(SB + 3) & 3>(cv[1], dv[1], cv[2], dv[2], w, o, co);
        base += 511;
        st4(out + base + ((SB + 3) & 3), o);
        st4(out + N + base + ((SB + 3) & 3), co);
    }
}

// Scalar pixel for leftover columns; 2-col window starting at input col wb.
__device__ __forceinline__ void edge_one(int ox, int wb, bool oddrow,
                                         const float* c0, const float* d0,
                                         const float* c1, const float* d1,
                                         const Wts& w, float* __restrict__ out,
                                         size_t N, size_t rowb) {
    float dd, cc;
    if ((ox & 1) == 0) {
        int li = (ox >> 1) - wb;
        float cva = li ? c0[1] : c0[0];
        float dva = li ? d0[1] : d0[0];
        if (!oddrow) {
            pixE(cva, dva, w, dd, cc);
        } else {
            float cvb = li ? c1[1] : c1[0];
            float dvb = li ? d1[1] : d1[0];
            pixE2(cva, dva, cvb, dvb, w, dd, cc);
        }
    } else {
        if (!oddrow) pixO(c0[0], d0[0], c0[1], d0[1], w, dd, cc);
        else         pixO2(c0[0], d0[0], c0[1], d0[1],
                           c1[0], d1[0], c1[1], d1[1], w, dd, cc);
    }
    __stcs(out + rowb + ox, dd);
    __stcs(out + N + rowb + ox, cc);
}

#define SM_ROWS 9
#define SM_COLS 132
#define SM_STRIDE (SM_ROWS * SM_COLS)   // 1188 floats per array

__global__ __launch_bounds__(256) void deconv_v10_kernel(
    const float* __restrict__ d,
    const float* __restrict__ cd,
    const float* __restrict__ sw,
    const float* __restrict__ bias,
    float* __restrict__ out)
{
    constexpr int W_ = 256, OH = 511, OW = 511;
    const size_t N = (size_t)256 * OH * OW;

    __shared__ float S_[14];
    __shared__ __align__(16) float T_[2 * SM_STRIDE];  // [cd | d] tiles

    int bc  = blockIdx.z;
    int c   = bc & 31;
    int bx  = blockIdx.x;          // 0..1  (col half)
    int by  = blockIdx.y;          // 0..31 (row band: input rows 8by..8by+8)
    int tx  = threadIdx.x;         // 0..63
    int ty  = threadIdx.y;         // 0..3
    int tid = ty * 64 + tx;

    size_t plane = (size_t)bc * (W_ * W_);
    const float* cp = cd + plane;
    const float* dp = d + plane;

    // ---- softplus prep (threads 0..9) ----
    if (tid < 9) {
        float x = sw[c * 9 + tid];
        S_[tid] = fmaxf(x, 0.0f) + log1pf(expf(-fabsf(x)));  // softplus
    }
    if (tid == 9) S_[13] = bias[c];

    // ---- cooperative dense staging of the block's input region ----
    // Rows 8by..8by+8 (clamp 255: clamped row's values unused), cols
    // 128bx + [0,131] with the float4 base clamped to 252 (duplicates land
    // in local cols no thread reads for bx=1).
    {
        const int F4R = SM_COLS / 4;            // 33 float4 per row
        const int TOT = 2 * SM_ROWS * F4R;      // 594
        for (int i = tid; i < TOT; i += 256) {
            int arr = i / (SM_ROWS * F4R);
            int rem = i - arr * (SM_ROWS * F4R);
            int row = rem / F4R;
            int f4  = rem - row * F4R;
            int gy  = 8 * by + row; if (gy > 255) gy = 255;
            int gx  = 128 * bx + 4 * f4; if (gx > 252) gx = 252;
            const float* src = (arr ? dp : cp) + gy * W_ + gx;
            float4 v = *reinterpret_cast<const float4*>(src);
            *reinterpret_cast<float4*>(
                &T_[arr * SM_STRIDE + row * SM_COLS + 4 * f4]) = v;
        }
    }
    __syncthreads();
    if (tid < 4) {
        float r;
        if      (tid == 0) r = S_[4];
        else if (tid == 1) r = S_[3] + S_[5];
        else if (tid == 2) r = S_[1] + S_[7];
        else               r = (S_[0] + S_[2]) + (S_[6] + S_[8]);
        S_[9 + tid] = 1.0f / (r + EPS_F);
    }
    __syncthreads();

    Wts w;
    w.s0 = S_[0]; w.s1 = S_[1]; w.s2 = S_[2]; w.s3 = S_[3]; w.s4 = S_[4];
    w.s5 = S_[5]; w.s6 = S_[6]; w.s7 = S_[7]; w.s8 = S_[8];
    w.ree = S_[9]; w.reo = S_[10]; w.roe = S_[11]; w.roo = S_[12];
    w.b = S_[13];

    int q  = bx * 64 + tx;        // col slot [0,127]
    int ry = by * 4 + ty;         // row group [0,127]
    bool pm = (ry != 127);        // output row 4ry+3 exists
    int SB = (-bc) & 3;           // shift of row oy=4ry

    // ---- window read from smem (all threads; LDS.64, 8B-aligned) ----
    float cv[3][4], dv[3][4];
#pragma unroll
    for (int i = 0; i < 3; i++) {
        const float* cb = &T_[(2 * ty + i) * SM_COLS + 2 * tx];
        const float* db = cb + SM_STRIDE;
        float2 a  = *reinterpret_cast<const float2*>(cb);
        float2 b2 = *reinterpret_cast<const float2*>(cb + 2);
        float2 e  = *reinterpret_cast<const float2*>(db);
        float2 f2 = *reinterpret_cast<const float2*>(db + 2);
        cv[i][0] = a.x; cv[i][1] = a.y; cv[i][2] = b2.x; cv[i][3] = b2.y;
        dv[i][0] = e.x; dv[i][1] = e.y; dv[i][2] = f2.x; dv[i][3] = f2.y;
    }

    if (q < 127) {
        size_t row0 = ((size_t)bc * OH + 4 * (size_t)ry) * OW;
        switch (SB) {
            case 0:  doRows<0>(cv, dv, w, out, N, row0, q, pm); break;
            case 1:  doRows<1>(cv, dv, w, out, N, row0, q, pm); break;
            case 2:  doRows<2>(cv, dv, w, out, N, row0, q, pm); break;
            default: doRows<3>(cv, dv, w, out, N, row0, q, pm); break;
        }
    } else {
        // Edge slot (q=127): head cols [0,S) from gmem; tail [S+508,511)
        // uses this thread's window (local cols 126,127 = global 254,255).
        float chh[3][2], dhh[3][2];
#pragma unroll
        for (int i = 0; i < 3; i++) {
            int r = 2 * ry + i; if (r > 255) r = 255;
            float2 a = *reinterpret_cast<const float2*>(cp + r * W_);
            float2 e = *reinterpret_cast<const float2*>(dp + r * W_);
            chh[i][0] = a.x; chh[i][1] = a.y;
            dhh[i][0] = e.x; dhh[i][1] = e.y;
        }
#pragma unroll
        for (int p = 0; p < 4; p++) {
            if (p == 3 && !pm) break;
            int S = (SB + p) & 3;
            int oy = 4 * ry + p;
            size_t rowb = ((size_t)bc * OH + oy) * OW;
            int r0 = (p <= 1) ? 0 : 1;
            bool oddrow = (p & 1);
            for (int ox = 0; ox < S; ox++)
                edge_one(ox, 0, oddrow, chh[r0], dhh[r0],
                         chh[r0 + 1], dhh[r0 + 1], w, out, N, rowb);
            for (int ox = S + 508; ox < 511; ox++)
                edge_one(ox, 254, oddrow, cv[r0], dv[r0],
                         cv[r0 + 1], dv[r0 + 1], w, out, N, rowb);
        }
    }
}

extern "C" void kernel_launch(void* const* d_in, const int* in_sizes, int n_in,
                              void* d_out, int out_size) {
    const float* d    = (const float*)d_in[0];
    const float* cd   = (const float*)d_in[1];
    const float* sw   = (const float*)d_in[2];
    const float* bias = (const float*)d_in[3];
    float* out = (float*)d_out;

    dim3 block(64, 4);
    dim3 grid(2, 32, 256);  // x: col halves; y: 8-row input bands; z: B*C
    deconv_v10_kernel<<<grid, block>>>(d, cd, sw, bias, out);
}

// round 11
// speedup vs baseline: 1.0890x; 1.0890x over previous
#include <cuda_runtime.h>

// StructNDeconv2D: depthwise conv_transpose2d (K=3, stride=2, pad=1) normalized
// convolution. OH = 2H-1 = 511 so every tap is in bounds.
//
// Round-11 = Round-9 body verbatim (best measured: kernel 104.5us, DRAM 73.7%)
// with occupancy/startup micro-tunes only:
//  - __launch_bounds__(256, 7): regs <=36 -> 7 CTAs/SM (56 warps, 87.5% occ)
//  - single-barrier prep: softplus by threads 0..8 -> smem -> one sync; each
//    thread computes the 4 parity-recips locally (MUFU.RCP) and reads bias
//    via __ldg broadcast. Removes a __syncthreads + divergent prep tail.
// Structural lessons locked in: R6/R8/R10 all showed wider/deeper/staged
// variants lose; R7 showed shuffles lose. Dense shifted-partition STG.128
// stores + 12 front-batched dense LDG.64 per thread is the optimum shape.

#define EPS_F 1e-20f

struct Wts {
    float s0, s1, s2, s3, s4, s5, s6, s7, s8;
    float ree, reo, roe, roo, b;
};

// ---- per-pixel math -------------------------------------------------------
__device__ __forceinline__ void pixE(float cv, float dv, const Wts& w,
                                     float& dd, float& cc) {
    float den = w.s4 * cv;
    dd = __fdividef(den * dv, den + EPS_F) + w.b;
    cc = den * w.ree;
}
__device__ __forceinline__ void pixO(float cL, float dL, float cR, float dR,
                                     const Wts& w, float& dd, float& cc) {
    float a = w.s3 * cR, b2 = w.s5 * cL;
    float den = a + b2;
    dd = __fdividef(fmaf(a, dR, b2 * dL), den + EPS_F) + w.b;
    cc = den * w.reo;
}
__device__ __forceinline__ void pixE2(float c0, float d0, float c1, float d1,
                                      const Wts& w, float& dd, float& cc) {
    float a = w.s1 * c1, b2 = w.s7 * c0;
    float den = a + b2;
    dd = __fdividef(fmaf(a, d1, b2 * d0), den + EPS_F) + w.b;
    cc = den * w.roe;
}
__device__ __forceinline__ void pixO2(float c0L, float d0L, float c0R, float d0R,
                                      float c1L, float d1L, float c1R, float d1R,
                                      const Wts& w, float& dd, float& cc) {
    float t0 = w.s0 * c1R, t2 = w.s2 * c1L, t6 = w.s6 * c0R, t8 = w.s8 * c0L;
    float den = (t0 + t2) + (t6 + t8);
    dd = __fdividef(fmaf(t0, d1R, fmaf(t2, d1L, fmaf(t6, d0R, t8 * d0L))),
                    den + EPS_F) + w.b;
    cc = den * w.roo;
}

// ---- 4-col chunks (outputs [S+4q, S+4q+4), window = input cols [2q..2q+3]) -
template<int S>
__device__ __forceinline__ void even_chunk(const float* cv, const float* dv,
                                           const Wts& w, float* o, float* co) {
    constexpr int h = S >> 1;
    if constexpr ((S & 1) == 0) {
        pixE(cv[h],   dv[h],                     w, o[0], co[0]);
        pixO(cv[h],   dv[h],   cv[h+1], dv[h+1], w, o[1], co[1]);
        pixE(cv[h+1], dv[h+1],                   w, o[2], co[2]);
        pixO(cv[h+1], dv[h+1], cv[h+2], dv[h+2], w, o[3], co[3]);
    } else {
        pixO(cv[h],   dv[h],   cv[h+1], dv[h+1], w, o[0], co[0]);
        pixE(cv[h+1], dv[h+1],                   w, o[1], co[1]);
        pixO(cv[h+1], dv[h+1], cv[h+2], dv[h+2], w, o[2], co[2]);
        pixE(cv[h+2], dv[h+2],                   w, o[3], co[3]);
    }
}
template<int S>
__device__ __forceinline__ void odd_chunk(const float* c0, const float* d0,
                                          const float* c1, const float* d1,
                                          const Wts& w, float* o, float* co) {
    constexpr int h = S >> 1;
    if constexpr ((S & 1) == 0) {
        pixE2(c0[h],   d0[h],   c1[h],   d1[h],   w, o[0], co[0]);
        pixO2(c0[h],   d0[h],   c0[h+1], d0[h+1],
              c1[h],   d1[h],   c1[h+1], d1[h+1], w, o[1], co[1]);
        pixE2(c0[h+1], d0[h+1], c1[h+1], d1[h+1], w, o[2], co[2]);
        pixO2(c0[h+1], d0[h+1], c0[h+2], d0[h+2],
              c1[h+1], d1[h+1], c1[h+2], d1[h+2], w, o[3], co[3]);
    } else {
        pixO2(c0[h],   d0[h],   c0[h+1], d0[h+1],
              c1[h],   d1[h],   c1[h+1], d1[h+1], w, o[0], co[0]);
        pixE2(c0[h+1], d0[h+1], c1[h+1], d1[h+1], w, o[1], co[1]);
        pixO2(c0[h+1], d0[h+1], c0[h+2], d0[h+2],
              c1[h+1], d1[h+1], c1[h+2], d1[h+2], w, o[2], co[2]);
        pixE2(c0[h+2], d0[h+2], c1[h+2], d1[h+2], w, o[3], co[3]);
    }
}

__device__ __forceinline__ void st4(float* p, const float* v) {
    __stcs(reinterpret_cast<float4*>(p), make_float4(v[0], v[1], v[2], v[3]));
}

// Thread's 4 output rows (oy = 4ry + p). Input rows cv[0..2] = y0..y0+2.
template<int SB>
__device__ __forceinline__ void doRows(const float cv[3][4], const float dv[3][4],
                                       const Wts& w, float* __restrict__ out,
                                       size_t N, size_t row0, int q, bool pm) {
    float o[4], co[4];
    size_t base = row0 + 4 * (size_t)q;

    even_chunk<SB>(cv[0], dv[0], w, o, co);
    st4(out + base + SB, o);
    st4(out + N + base + SB, co);

    odd_chunk<(SB + 1) & 3>(cv[0], dv[0], cv[1], dv[1], w, o, co);
    base += 511;
    st4(out + base + ((SB + 1) & 3), o);
    st4(out + N + base + ((SB + 1) & 3), co);

    even_chunk<(SB + 2) & 3>(cv[1], dv[1], w, o, co);
    base += 511;
    st4(out + base + ((SB + 2) & 3), o);
    st4(out + N + base + ((SB + 2) & 3), co);

    if (pm) {
        odd_chunk<(SB + 3) & 3>(cv[1], dv[1], cv[2], dv[2], w, o, co);
        base += 511;
        st4(out + base + ((SB + 3) & 3), o);
        st4(out + N + base + ((SB + 3) & 3), co);
    }
}

// Scalar pixel for leftover columns; 2-col window starting at input col wb.
__device__ __forceinline__ void edge_one(int ox, int wb, bool oddrow,
                                         const float* c0, const float* d0,
                                         const float* c1, const float* d1,
                                         const Wts& w, float* __restrict__ out,
                                         size_t N, size_t rowb) {
    float dd, cc;
    if ((ox & 1) == 0) {
        int li = (ox >> 1) - wb;
        float cva = li ? c0[1] : c0[0];
        float dva = li ? d0[1] : d0[0];
        if (!oddrow) {
            pixE(cva, dva, w, dd, cc);
        } else {
            float cvb = li ? c1[1] : c1[0];
            float dvb = li ? d1[1] : d1[0];
            pixE2(cva, dva, cvb, dvb, w, dd, cc);
        }
    } else {
        if (!oddrow) pixO(c0[0], d0[0], c0[1], d0[1], w, dd, cc);
        else         pixO2(c0[0], d0[0], c0[1], d0[1],
                           c1[0], d1[0], c1[1], d1[1], w, dd, cc);
    }
    __stcs(out + rowb + ox, dd);
    __stcs(out + N + rowb + ox, cc);
}

__global__ __launch_bounds__(256, 7) void deconv_v11_kernel(
    const float* __restrict__ d,
    const float* __restrict__ cd,
    const float* __restrict__ sw,
    const float* __restrict__ bias,
    float* __restrict__ out)
{
    constexpr int W_ = 256, OH = 511, OW = 511;

    // ---- single-barrier prep: softplus into smem, recips per-thread ----
    __shared__ float S_[9];
    int bc  = blockIdx.z;
    int c   = bc & 31;
    int tid = threadIdx.y * 64 + threadIdx.x;

    if (tid < 9) {
        float x = sw[c * 9 + tid];
        S_[tid] = fmaxf(x, 0.0f) + log1pf(expf(-fabsf(x)));  // softplus
    }
    __syncthreads();

    Wts w;
    w.s0 = S_[0]; w.s1 = S_[1]; w.s2 = S_[2]; w.s3 = S_[3]; w.s4 = S_[4];
    w.s5 = S_[5]; w.s6 = S_[6]; w.s7 = S_[7]; w.s8 = S_[8];
    w.ree = __fdividef(1.0f, w.s4 + EPS_F);
    w.reo = __fdividef(1.0f, w.s3 + w.s5 + EPS_F);
    w.roe = __fdividef(1.0f, w.s1 + w.s7 + EPS_F);
    w.roo = __fdividef(1.0f, (w.s0 + w.s2) + (w.s6 + w.s8) + EPS_F);
    w.b   = __ldg(bias + c);

    int q  = blockIdx.x * 64 + threadIdx.x;   // col slot [0,127]
    int ry = blockIdx.y * 4 + threadIdx.y;    // row group [0,127]
    int y0 = ry * 2;                          // first input row

    size_t plane = (size_t)bc * (W_ * W_);
    const float* cp = cd + plane;
    const float* dp = d + plane;
    size_t N = (size_t)256 * OH * OW;
    bool pm = (ry != 127);                    // output row 4ry+3 exists

    int SB = (-bc) & 3;                       // shift of row oy=4ry

    if (q < 127) {
        int X = 2 * q;
        float cv[3][4], dv[3][4];
#pragma unroll
        for (int i = 0; i < 3; i++) {
            int r = y0 + i; if (r > 255) r = 255;  // clamped row unused
            const float* cr = cp + r * W_ + X;
            const float* dr = dp + r * W_ + X;
            float2 a  = *reinterpret_cast<const float2*>(cr);
            float2 b2 = *reinterpret_cast<const float2*>(cr + 2);
            float2 e  = *reinterpret_cast<const float2*>(dr);
            float2 f2 = *reinterpret_cast<const float2*>(dr + 2);
            cv[i][0] = a.x; cv[i][1] = a.y; cv[i][2] = b2.x; cv[i][3] = b2.y;
            dv[i][0] = e.x; dv[i][1] = e.y; dv[i][2] = f2.x; dv[i][3] = f2.y;
        }
        size_t row0 = ((size_t)bc * OH + 4 * (size_t)ry) * OW;
        switch (SB) {
            case 0:  doRows<0>(cv, dv, w, out, N, row0, q, pm); break;
            case 1:  doRows<1>(cv, dv, w, out, N, row0, q, pm); break;
            case 2:  doRows<2>(cv, dv, w, out, N, row0, q, pm); break;
            default: doRows<3>(cv, dv, w, out, N, row0, q, pm); break;
        }
    } else {
        // Leftovers: head [0,S) and tail [S+508, 511) per output row.
        float chh[3][2], dhh[3][2], ctt[3][2], dtt[3][2];
#pragma unroll
        for (int i = 0; i < 3; i++) {
            int r = y0 + i; if (r > 255) r = 255;
            const float* crow = cp + r * W_;
            const float* drow = dp + r * W_;
            float2 a  = *reinterpret_cast<const float2*>(crow);
            float2 b2 = *reinterpret_cast<const float2*>(crow + 254);
            float2 e  = *reinterpret_cast<const float2*>(drow);
            float2 f2 = *reinterpret_cast<const float2*>(drow + 254);
            chh[i][0] = a.x; chh[i][1] = a.y; ctt[i][0] = b2.x; ctt[i][1] = b2.y;
            dhh[i][0] = e.x; dhh[i][1] = e.y; dtt[i][0] = f2.x; dtt[i][1] = f2.y;
        }
#pragma unroll
        for (int p = 0; p < 4; p++) {
            if (p == 3 && !pm) break;
            int S = (SB + p) & 3;
            int oy = 4 * ry + p;
            size_t rowb = ((size_t)bc * OH + oy) * OW;
            int r0 = (p <= 1) ? 0 : 1;
            bool oddrow = (p & 1);
            for (int ox = 0; ox < S; ox++)
                edge_one(ox, 0, oddrow, chh[r0], dhh[r0],
                         chh[r0 + 1], dhh[r0 + 1], w, out, N, rowb);
            for (int ox = S + 508; ox < 511; ox++)
                edge_one(ox, 254, oddrow, ctt[r0], dtt[r0],
                         ctt[r0 + 1], dtt[r0 + 1], w, out, N, rowb);
        }
    }
}

extern "C" void kernel_launch(void* const* d_in, const int* in_sizes, int n_in,
                              void* d_out, int out_size) {
    const float* d    = (const float*)d_in[0];
    const float* cd   = (const float*)d_in[1];
    const float* sw   = (const float*)d_in[2];
    const float* bias = (const float*)d_in[3];
    float* out = (float*)d_out;

    dim3 block(64, 4);
    dim3 grid(2, 32, 256);  // x: 128 col slots/64; y: 128 row groups/4; z: B*C
    deconv_v11_kernel<<<grid, block>>>(d, cd, sw, bias, out);
}

// round 12
// speedup vs baseline: 1.1658x; 1.0705x over previous
#include <cuda_runtime.h>

// StructNDeconv2D: depthwise conv_transpose2d (K=3, stride=2, pad=1) normalized
// convolution. OH = 2H-1 = 511 so every tap is in bounds.
//
// Round-12 = Round-9 body (best measured kernel shape: dense shifted-partition
// STG.128 stores, 4 output rows x 4 output cols per thread, 12 front-batched
// LDG.64, 16384 blocks, regs ~40) + Round-11's single-barrier prep (softplus
// by threads 0..8 into smem, one sync, per-thread recips + __ldg bias) with
// NO minBlocksPerMultiprocessor clamp: R11 proved forcing 7 CTAs/SM squeezes
// regs 40->32 and destroys per-warp MLP (DRAM 73.7% -> 70.3%).
//
// Shift S=(oy-bc)&3 16B-aligns every 4-col output chunk; a thread's first row
// has oy=4ry==0 mod 4 so base shift SB=(-bc)&3 is block-uniform (template
// dispatch). Col slot 127 handles the 3 leftover cols per row (head+tail).

#define EPS_F 1e-20f

struct Wts {
    float s0, s1, s2, s3, s4, s5, s6, s7, s8;
    float ree, reo, roe, roo, b;
};

// ---- per-pixel math -------------------------------------------------------
__device__ __forceinline__ void pixE(float cv, float dv, const Wts& w,
                                     float& dd, float& cc) {
    float den = w.s4 * cv;
    dd = __fdividef(den * dv, den + EPS_F) + w.b;
    cc = den * w.ree;
}
__device__ __forceinline__ void pixO(float cL, float dL, float cR, float dR,
                                     const Wts& w, float& dd, float& cc) {
    float a = w.s3 * cR, b2 = w.s5 * cL;
    float den = a + b2;
    dd = __fdividef(fmaf(a, dR, b2 * dL), den + EPS_F) + w.b;
    cc = den * w.reo;
}
__device__ __forceinline__ void pixE2(float c0, float d0, float c1, float d1,
                                      const Wts& w, float& dd, float& cc) {
    float a = w.s1 * c1, b2 = w.s7 * c0;
    float den = a + b2;
    dd = __fdividef(fmaf(a, d1, b2 * d0), den + EPS_F) + w.b;
    cc = den * w.roe;
}
__device__ __forceinline__ void pixO2(float c0L, float d0L, float c0R, float d0R,
                                      float c1L, float d1L, float c1R, float d1R,
                                      const Wts& w, float& dd, float& cc) {
    float t0 = w.s0 * c1R, t2 = w.s2 * c1L, t6 = w.s6 * c0R, t8 = w.s8 * c0L;
    float den = (t0 + t2) + (t6 + t8);
    dd = __fdividef(fmaf(t0, d1R, fmaf(t2, d1L, fmaf(t6, d0R, t8 * d0L))),
                    den + EPS_F) + w.b;
    cc = den * w.roo;
}

// ---- 4-col chunks (outputs [S+4q, S+4q+4), window = input cols [2q..2q+3]) -
template<int S>
__device__ __forceinline__ void even_chunk(const float* cv, const float* dv,
                                           const Wts& w, float* o, float* co) {
    constexpr int h = S >> 1;
    if constexpr ((S & 1) == 0) {
        pixE(cv[h],   dv[h],                     w, o[0], co[0]);
        pixO(cv[h],   dv[h],   cv[h+1], dv[h+1], w, o[1], co[1]);
        pixE(cv[h+1], dv[h+1],                   w, o[2], co[2]);
        pixO(cv[h+1], dv[h+1], cv[h+2], dv[h+2], w, o[3], co[3]);
    } else {
        pixO(cv[h],   dv[h],   cv[h+1], dv[h+1], w, o[0], co[0]);
        pixE(cv[h+1], dv[h+1],                   w, o[1], co[1]);
        pixO(cv[h+1], dv[h+1], cv[h+2], dv[h+2], w, o[2], co[2]);
        pixE(cv[h+2], dv[h+2],                   w, o[3], co[3]);
    }
}
template<int S>
__device__ __forceinline__ void odd_chunk(const float* c0, const float* d0,
                                          const float* c1, const float* d1,
                                          const Wts& w, float* o, float* co) {
    constexpr int h = S >> 1;
    if constexpr ((S & 1) == 0) {
        pixE2(c0[h],   d0[h],   c1[h],   d1[h],   w, o[0], co[0]);
        pixO2(c0[h],   d0[h],   c0[h+1], d0[h+1],
              c1[h],   d1[h],   c1[h+1], d1[h+1], w, o[1], co[1]);
        pixE2(c0[h+1], d0[h+1], c1[h+1], d1[h+1], w, o[2], co[2]);
        pixO2(c0[h+1], d0[h+1], c0[h+2], d0[h+2],
              c1[h+1], d1[h+1], c1[h+2], d1[h+2], w, o[3], co[3]);
    } else {
        pixO2(c0[h],   d0[h],   c0[h+1], d0[h+1],
              c1[h],   d1[h],   c1[h+1], d1[h+1], w, o[0], co[0]);
        pixE2(c0[h+1], d0[h+1], c1[h+1], d1[h+1], w, o[1], co[1]);
        pixO2(c0[h+1], d0[h+1], c0[h+2], d0[h+2],
              c1[h+1], d1[h+1], c1[h+2], d1[h+2], w, o[2], co[2]);
        pixE2(c0[h+2], d0[h+2], c1[h+2], d1[h+2], w, o[3], co[3]);
    }
}

__device__ __forceinline__ void st4(float* p, const float* v) {
    __stcs(reinterpret_cast<float4*>(p), make_float4(v[0], v[1], v[2], v[3]));
}

// Thread's 4 output rows (oy = 4ry + p). Input rows cv[0..2] = y0..y0+2.
template<int SB>
__device__ __forceinline__ void doRows(const float cv[3][4], const float dv[3][4],
                                       const Wts& w, float* __restrict__ out,
                                       size_t N, size_t row0, int q, bool pm) {
    float o[4], co[4];
    size_t base = row0 + 4 * (size_t)q;

    even_chunk<SB>(cv[0], dv[0], w, o, co);
    st4(out + base + SB, o);
    st4(out + N + base + SB, co);

    odd_chunk<(SB + 1) & 3>(cv[0], dv[0], cv[1], dv[1], w, o, co);
    base += 511;
    st4(out + base + ((SB + 1) & 3), o);
    st4(out + N + base + ((SB + 1) & 3), co);

    even_chunk<(SB + 2) & 3>(cv[1], dv[1], w, o, co);
    base += 511;
    st4(out + base + ((SB + 2) & 3), o);
    st4(out + N + base + ((SB + 2) & 3), co);

    if (pm) {
        odd_chunk<(SB + 3) & 3>(cv[1], dv[1], cv[2], dv[2], w, o, co);
        base += 511;
        st4(out + base + ((SB + 3) & 3), o);
        st4(out + N + base + ((SB + 3) & 3), co);
    }
}

// Scalar pixel for leftover columns; 2-col window starting at input col wb.
__device__ __forceinline__ void edge_one(int ox, int wb, bool oddrow,
                                         const float* c0, const float* d0,
                                         const float* c1, const float* d1,
                                         const Wts& w, float* __restrict__ out,
                                         size_t N, size_t rowb) {
    float dd, cc;
    if ((ox & 1) == 0) {
        int li = (ox >> 1) - wb;
        float cva = li ? c0[1] : c0[0];
        float dva = li ? d0[1] : d0[0];
        if (!oddrow) {
            pixE(cva, dva, w, dd, cc);
        } else {
            float cvb = li ? c1[1] : c1[0];
            float dvb = li ? d1[1] : d1[0];
            pixE2(cva, dva, cvb, dvb, w, dd, cc);
        }
    } else {
        if (!oddrow) pixO(c0[0], d0[0], c0[1], d0[1], w, dd, cc);
        else         pixO2(c0[0], d0[0], c0[1], d0[1],
                           c1[0], d1[0], c1[1], d1[1], w, dd, cc);
    }
    __stcs(out + rowb + ox, dd);
    __stcs(out + N + rowb + ox, cc);
}

__global__ __launch_bounds__(256) void deconv_v12_kernel(
    const float* __restrict__ d,
    const float* __restrict__ cd,
    const float* __restrict__ sw,
    const float* __restrict__ bias,
    float* __restrict__ out)
{
    constexpr int W_ = 256, OH = 511, OW = 511;

    // ---- single-barrier prep: softplus into smem, recips per-thread ----
    __shared__ float S_[9];
    int bc  = blockIdx.z;
    int c   = bc & 31;
    int tid = threadIdx.y * 64 + threadIdx.x;

    if (tid < 9) {
        float x = sw[c * 9 + tid];
        S_[tid] = fmaxf(x, 0.0f) + log1pf(expf(-fabsf(x)));  // softplus
    }
    __syncthreads();

    Wts w;
    w.s0 = S_[0]; w.s1 = S_[1]; w.s2 = S_[2]; w.s3 = S_[3]; w.s4 = S_[4];
    w.s5 = S_[5]; w.s6 = S_[6]; w.s7 = S_[7]; w.s8 = S_[8];
    w.ree = __fdividef(1.0f, w.s4 + EPS_F);
    w.reo = __fdividef(1.0f, w.s3 + w.s5 + EPS_F);
    w.roe = __fdividef(1.0f, w.s1 + w.s7 + EPS_F);
    w.roo = __fdividef(1.0f, (w.s0 + w.s2) + (w.s6 + w.s8) + EPS_F);
    w.b   = __ldg(bias + c);

    int q  = blockIdx.x * 64 + threadIdx.x;   // col slot [0,127]
    int ry = blockIdx.y * 4 + threadIdx.y;    // row group [0,127]
    int y0 = ry * 2;                          // first input row

    size_t plane = (size_t)bc * (W_ * W_);
    const float* cp = cd + plane;
    const float* dp = d + plane;
    size_t N = (size_t)256 * OH * OW;
    bool pm = (ry != 127);                    // output row 4ry+3 exists

    int SB = (-bc) & 3;                       // shift of row oy=4ry

    if (q < 127) {
        int X = 2 * q;
        float cv[3][4], dv[3][4];
#pragma unroll
        for (int i = 0; i < 3; i++) {
            int r = y0 + i; if (r > 255) r = 255;  // clamped row unused
            const float* cr = cp + r * W_ + X;
            const float* dr = dp + r * W_ + X;
            float2 a  = *reinterpret_cast<const float2*>(cr);
            float2 b2 = *reinterpret_cast<const float2*>(cr + 2);
            float2 e  = *reinterpret_cast<const float2*>(dr);
            float2 f2 = *reinterpret_cast<const float2*>(dr + 2);
            cv[i][0] = a.x; cv[i][1] = a.y; cv[i][2] = b2.x; cv[i][3] = b2.y;
            dv[i][0] = e.x; dv[i][1] = e.y; dv[i][2] = f2.x; dv[i][3] = f2.y;
        }
        size_t row0 = ((size_t)bc * OH + 4 * (size_t)ry) * OW;
        switch (SB) {
            case 0:  doRows<0>(cv, dv, w, out, N, row0, q, pm); break;
            case 1:  doRows<1>(cv, dv, w, out, N, row0, q, pm); break;
            case 2:  doRows<2>(cv, dv, w, out, N, row0, q, pm); break;
            default: doRows<3>(cv, dv, w, out, N, row0, q, pm); break;
        }
    } else {
        // Leftovers: head [0,S) and tail [S+508, 511) per output row.
        float chh[3][2], dhh[3][2], ctt[3][2], dtt[3][2];
#pragma unroll
        for (int i = 0; i < 3; i++) {
            int r = y0 + i; if (r > 255) r = 255;
            const float* crow = cp + r * W_;
            const float* drow = dp + r * W_;
            float2 a  = *reinterpret_cast<const float2*>(crow);
            float2 b2 = *reinterpret_cast<const float2*>(crow + 254);
            float2 e  = *reinterpret_cast<const float2*>(drow);
            float2 f2 = *reinterpret_cast<const float2*>(drow + 254);
            chh[i][0] = a.x; chh[i][1] = a.y; ctt[i][0] = b2.x; ctt[i][1] = b2.y;
            dhh[i][0] = e.x; dhh[i][1] = e.y; dtt[i][0] = f2.x; dtt[i][1] = f2.y;
        }
#pragma unroll
        for (int p = 0; p < 4; p++) {
            if (p == 3 && !pm) break;
            int S = (SB + p) & 3;
            int oy = 4 * ry + p;
            size_t rowb = ((size_t)bc * OH + oy) * OW;
            int r0 = (p <= 1) ? 0 : 1;
            bool oddrow = (p & 1);
            for (int ox = 0; ox < S; ox++)
                edge_one(ox, 0, oddrow, chh[r0], dhh[r0],
                         chh[r0 + 1], dhh[r0 + 1], w, out, N, rowb);
            for (int ox = S + 508; ox < 511; ox++)
                edge_one(ox, 254, oddrow, ctt[r0], dtt[r0],
                         ctt[r0 + 1], dtt[r0 + 1], w, out, N, rowb);
        }
    }
}

extern "C" void kernel_launch(void* const* d_in, const int* in_sizes, int n_in,
                              void* d_out, int out_size) {
    const float* d    = (const float*)d_in[0];
    const float* cd   = (const float*)d_in[1];
    const float* sw   = (const float*)d_in[2];
    const float* bias = (const float*)d_in[3];
    float* out = (float*)d_out;

    dim3 block(64, 4);
    dim3 grid(2, 32, 256);  // x: 128 col slots/64; y: 128 row groups/4; z: B*C
    deconv_v12_kernel<<<grid, block>>>(d, cd, sw, bias, out);
}